// round 2
// baseline (speedup 1.0000x reference)
#include <cuda_runtime.h>
#include <cstdint>
#include <cstdio>

// ---------------- problem constants ----------------
#define NP 100000
#define NS 50000
#define PD 1024
#define SD 512
#define HF 64
#define EPN 3200000
#define ESN 1600000
#define ELN 2000000

// ---------------- device scratch (static; no allocation allowed) ----------------
__device__ float g_bufP0[(size_t)NP * HF];
__device__ float g_bufP1[(size_t)NP * HF];
__device__ float g_bufS0[(size_t)NS * HF];
__device__ float g_bufS1[(size_t)NS * HF];
__device__ float g_dinvP[NP];
__device__ float g_dinvS[NS];
__device__ int   g_rowP[NP + 1];
__device__ int   g_rowS[NS + 1];
__device__ int   g_curP[NP];
__device__ int   g_curS[NS];
__device__ int   g_srcP[EPN];
__device__ int   g_srcS[ESN];
__device__ float g_Wc[128 * 64 + 64];   // Wcomb [128,64] row-major, then bcomb[64]
__device__ int   g_bsum[256];

// ---------------- CSR build ----------------
__global__ void k_count(const int* __restrict__ dst, int E, int* __restrict__ cnt) {
    int e = blockIdx.x * blockDim.x + threadIdx.x;
    if (e < E) atomicAdd(&cnt[dst[e]], 1);
}

// inclusive scan per 1024-block; writes exclusive (pre-offset) starts, block totals
__global__ void k_scan1(const int* __restrict__ cnt, int* __restrict__ rowStart,
                        int* __restrict__ blockSums, int N) {
    __shared__ int sh[1024];
    int i = blockIdx.x * 1024 + threadIdx.x;
    int v = (i < N) ? cnt[i] : 0;
    sh[threadIdx.x] = v;
    __syncthreads();
    for (int off = 1; off < 1024; off <<= 1) {
        int t = 0;
        if ((int)threadIdx.x >= off) t = sh[threadIdx.x - off];
        __syncthreads();
        sh[threadIdx.x] += t;
        __syncthreads();
    }
    int incl = sh[threadIdx.x];
    if (i < N) rowStart[i] = incl - v;        // exclusive within block
    if (threadIdx.x == 1023) blockSums[blockIdx.x] = incl;
}

__global__ void k_scan2(int* __restrict__ blockSums, int nb) {
    __shared__ int sh[1024];
    int v = ((int)threadIdx.x < nb) ? blockSums[threadIdx.x] : 0;
    sh[threadIdx.x] = v;
    __syncthreads();
    for (int off = 1; off < 1024; off <<= 1) {
        int t = 0;
        if ((int)threadIdx.x >= off) t = sh[threadIdx.x - off];
        __syncthreads();
        sh[threadIdx.x] += t;
        __syncthreads();
    }
    if ((int)threadIdx.x < nb) blockSums[threadIdx.x] = sh[threadIdx.x] - v;  // exclusive
}

__global__ void k_scan3(int* __restrict__ rowStart, int* __restrict__ cursor,
                        const int* __restrict__ blockSums, int N, int E) {
    int i = blockIdx.x * blockDim.x + threadIdx.x;
    if (i < N) {
        int r = rowStart[i] + blockSums[i >> 10];
        rowStart[i] = r;
        cursor[i]   = r;
    }
    if (i == 0) rowStart[N] = E;
}

__global__ void k_fill(const int* __restrict__ src, const int* __restrict__ dst,
                       int E, int* __restrict__ cursor, int* __restrict__ srcs) {
    int e = blockIdx.x * blockDim.x + threadIdx.x;
    if (e < E) {
        int d = dst[e];
        int p = atomicAdd(&cursor[d], 1);
        srcs[p] = src[e];
    }
}

__global__ void k_dinv(const int* __restrict__ row, float* __restrict__ dinv, int N) {
    int i = blockIdx.x * blockDim.x + threadIdx.x;
    if (i < N) {
        int deg = row[i + 1] - row[i] + 1;   // +1 self loop
        dinv[i] = rsqrtf((float)deg);
    }
}

// ---------------- fp32 GEMM: Y[M,64] = X[M,K] @ W[K,64], K % 16 == 0 ----------------
#define TM 128
#define TK 16
__global__ __launch_bounds__(256) void k_gemm(const float* __restrict__ X,
                                              const float* __restrict__ W,
                                              float* __restrict__ Y, int M, int K) {
    __shared__ float Xs[TK][TM];   // transposed: Xs[kk][row]
    __shared__ float Ws[TK][HF];

    int tid = threadIdx.x;
    int tx = tid & 15;          // col group 0..15 -> cols tx*4..tx*4+3
    int ty = tid >> 4;          // row group 0..15 -> rows ty*8..ty*8+7
    int row0 = blockIdx.x * TM;
    int c0 = tx * 4;

    float acc[8][4];
#pragma unroll
    for (int i = 0; i < 8; i++)
#pragma unroll
        for (int j = 0; j < 4; j++) acc[i][j] = 0.f;

    for (int kt = 0; kt < K; kt += TK) {
        // load X tile: 128 rows x 16 k, 512 float4, 2 per thread, store transposed
#pragma unroll
        for (int l = 0; l < 2; l++) {
            int idx = tid + l * 256;
            int r = idx >> 2;
            int kk4 = (idx & 3) * 4;
            float4 v = make_float4(0.f, 0.f, 0.f, 0.f);
            int gr = row0 + r;
            if (gr < M) v = *(const float4*)(X + (size_t)gr * K + kt + kk4);
            Xs[kk4 + 0][r] = v.x;
            Xs[kk4 + 1][r] = v.y;
            Xs[kk4 + 2][r] = v.z;
            Xs[kk4 + 3][r] = v.w;
        }
        // load W tile: 16 x 64 = 256 float4, 1 per thread
        {
            int kk = tid >> 4;
            int c4 = (tid & 15) * 4;
            *(float4*)&Ws[kk][c4] = *(const float4*)(W + (size_t)(kt + kk) * HF + c4);
        }
        __syncthreads();
#pragma unroll
        for (int kk = 0; kk < TK; kk++) {
            float4 wv = *(const float4*)&Ws[kk][c0];
            float4 xa = *(const float4*)&Xs[kk][ty * 8];
            float4 xb = *(const float4*)&Xs[kk][ty * 8 + 4];
            float xv[8] = {xa.x, xa.y, xa.z, xa.w, xb.x, xb.y, xb.z, xb.w};
#pragma unroll
            for (int i = 0; i < 8; i++) {
                acc[i][0] += xv[i] * wv.x;
                acc[i][1] += xv[i] * wv.y;
                acc[i][2] += xv[i] * wv.z;
                acc[i][3] += xv[i] * wv.w;
            }
        }
        __syncthreads();
    }
#pragma unroll
    for (int i = 0; i < 8; i++) {
        int gr = row0 + ty * 8 + i;
        if (gr < M) {
            float4 v = make_float4(acc[i][0], acc[i][1], acc[i][2], acc[i][3]);
            *(float4*)(Y + (size_t)gr * HF + c0) = v;
        }
    }
}

// ---------------- GCN aggregation (CSR, warp per dst node) ----------------
// out[dst] = dinv[dst]*( h[dst]*dinv[dst] + sum_src h[src]*dinv[src] ) + bias
__global__ void k_aggregate(const float* __restrict__ H, float* __restrict__ OUT,
                            const int* __restrict__ row, const int* __restrict__ srcs,
                            const float* __restrict__ dinv, const float* __restrict__ bias,
                            int N) {
    int warp = (blockIdx.x * blockDim.x + threadIdx.x) >> 5;
    int lane = threadIdx.x & 31;
    if (warp >= N) return;
    int dst = warp;
    float di = dinv[dst];
    const float2* Hp = (const float2*)H;
    float2 hs = Hp[(size_t)dst * 32 + lane];
    float2 acc = make_float2(hs.x * di, hs.y * di);
    int s = row[dst], e = row[dst + 1];
    for (int i = s; i < e; i++) {
        int src = srcs[i];                 // warp-uniform broadcast load
        float ds = dinv[src];
        float2 h = Hp[(size_t)src * 32 + lane];
        acc.x += h.x * ds;
        acc.y += h.y * ds;
    }
    float2 b2 = ((const float2*)bias)[lane];
    float2 o = make_float2(acc.x * di + b2.x, acc.y * di + b2.y);
    ((float2*)OUT)[(size_t)dst * 32 + lane] = o;
}

// ---------------- fold Wproj/Wl1 into Wcomb, bcomb ----------------
__global__ void k_prepWc(const float* __restrict__ Wproj, const float* __restrict__ bproj,
                         const float* __restrict__ Wl1, const float* __restrict__ bl1,
                         float* __restrict__ Wc) {
    __shared__ float sWl1[128 * 64];
    for (int i = threadIdx.x; i < 128 * 64; i += blockDim.x) sWl1[i] = Wl1[i];
    __syncthreads();
    for (int o = threadIdx.x; o < 128 * 64; o += blockDim.x) {
        int i = o >> 6, j = o & 63;
        float s = 0.f;
        for (int k = 0; k < 128; k++) s += Wproj[i * 128 + k] * sWl1[k * 64 + j];
        Wc[o] = s;
    }
    for (int j = threadIdx.x; j < 64; j += blockDim.x) {
        float s = bl1[j];
        for (int k = 0; k < 128; k++) s += bproj[k] * sWl1[k * 64 + j];
        Wc[128 * 64 + j] = s;
    }
}

// ---------------- link predictor: out[e] = relu(Ap[ep]+As[es]+bc) . wl2 + bl2 ----------------
__global__ void k_link(const float* __restrict__ Ap, const float* __restrict__ As,
                       const int* __restrict__ ep, const int* __restrict__ es,
                       const float* __restrict__ bc, const float* __restrict__ wl2,
                       const float* __restrict__ bl2, float* __restrict__ out, int EL) {
    int warp = (blockIdx.x * blockDim.x + threadIdx.x) >> 5;
    int lane = threadIdx.x & 31;
    if (warp >= EL) return;
    int p = ep[warp];
    int s = es[warp];
    float2 a = ((const float2*)Ap)[(size_t)p * 32 + lane];
    float2 b = ((const float2*)As)[(size_t)s * 32 + lane];
    float2 c = ((const float2*)bc)[lane];
    float hx = fmaxf(a.x + b.x + c.x, 0.f);
    float hy = fmaxf(a.y + b.y + c.y, 0.f);
    float2 w = ((const float2*)wl2)[lane];
    float part = hx * w.x + hy * w.y;
#pragma unroll
    for (int off = 16; off; off >>= 1) part += __shfl_xor_sync(0xffffffffu, part, off);
    if (lane == 0) out[warp] = part + bl2[0];
}

// ---------------- host orchestration ----------------
static inline int cdiv(int a, int b) { return (a + b - 1) / b; }

extern "C" void kernel_launch(void* const* d_in, const int* in_sizes, int n_in,
                              void* d_out, int out_size) {
    const float* x_p  = (const float*)d_in[0];
    const float* x_s  = (const float*)d_in[1];
    const int*   ei_p = (const int*)d_in[2];
    const int*   ei_s = (const int*)d_in[3];
    const int*   ed_p = (const int*)d_in[4];
    const int*   ed_s = (const int*)d_in[5];
    const float* Wp1 = (const float*)d_in[6];
    const float* bp1 = (const float*)d_in[7];
    const float* Ws1 = (const float*)d_in[8];
    const float* bs1 = (const float*)d_in[9];
    const float* Wp2 = (const float*)d_in[10];
    const float* bp2 = (const float*)d_in[11];
    const float* Ws2 = (const float*)d_in[12];
    const float* bs2 = (const float*)d_in[13];
    const float* Wproj = (const float*)d_in[14];
    const float* bproj = (const float*)d_in[15];
    const float* Wl1 = (const float*)d_in[16];
    const float* bl1 = (const float*)d_in[17];
    const float* Wl2 = (const float*)d_in[18];
    const float* bl2 = (const float*)d_in[19];
    float* out = (float*)d_out;

    float *bufP0, *bufP1, *bufS0, *bufS1, *dinvP, *dinvS, *Wc;
    int *rowP, *rowS, *curP, *curS, *srcP, *srcS, *bsum;
    cudaGetSymbolAddress((void**)&bufP0, g_bufP0);
    cudaGetSymbolAddress((void**)&bufP1, g_bufP1);
    cudaGetSymbolAddress((void**)&bufS0, g_bufS0);
    cudaGetSymbolAddress((void**)&bufS1, g_bufS1);
    cudaGetSymbolAddress((void**)&dinvP, g_dinvP);
    cudaGetSymbolAddress((void**)&dinvS, g_dinvS);
    cudaGetSymbolAddress((void**)&rowP,  g_rowP);
    cudaGetSymbolAddress((void**)&rowS,  g_rowS);
    cudaGetSymbolAddress((void**)&curP,  g_curP);
    cudaGetSymbolAddress((void**)&curS,  g_curS);
    cudaGetSymbolAddress((void**)&srcP,  g_srcP);
    cudaGetSymbolAddress((void**)&srcS,  g_srcS);
    cudaGetSymbolAddress((void**)&Wc,    g_Wc);
    cudaGetSymbolAddress((void**)&bsum,  g_bsum);

    const int EP = in_sizes[2] / 2;
    const int ES = in_sizes[3] / 2;
    const int EL = in_sizes[4];

    // ---- CSR build: protein ----
    cudaMemsetAsync(curP, 0, NP * sizeof(int));
    k_count<<<cdiv(EP, 256), 256>>>(ei_p + EP, EP, curP);
    {
        int nb = cdiv(NP, 1024);
        k_scan1<<<nb, 1024>>>(curP, rowP, bsum, NP);
        k_scan2<<<1, 1024>>>(bsum, nb);
        k_scan3<<<cdiv(NP, 256), 256>>>(rowP, curP, bsum, NP, EP);
    }
    k_fill<<<cdiv(EP, 256), 256>>>(ei_p, ei_p + EP, EP, curP, srcP);
    k_dinv<<<cdiv(NP, 256), 256>>>(rowP, dinvP, NP);

    // ---- CSR build: substrate ----
    cudaMemsetAsync(curS, 0, NS * sizeof(int));
    k_count<<<cdiv(ES, 256), 256>>>(ei_s + ES, ES, curS);
    {
        int nb = cdiv(NS, 1024);
        k_scan1<<<nb, 1024>>>(curS, rowS, bsum, NS);
        k_scan2<<<1, 1024>>>(bsum, nb);
        k_scan3<<<cdiv(NS, 256), 256>>>(rowS, curS, bsum, NS, ES);
    }
    k_fill<<<cdiv(ES, 256), 256>>>(ei_s, ei_s + ES, ES, curS, srcS);
    k_dinv<<<cdiv(NS, 256), 256>>>(rowS, dinvS, NS);

    // ---- fold link MLP weights ----
    k_prepWc<<<1, 256>>>(Wproj, bproj, Wl1, bl1, Wc);

    // ---- protein GCN ----
    k_gemm<<<cdiv(NP, TM), 256>>>(x_p, Wp1, bufP0, NP, PD);
    k_aggregate<<<cdiv(NP * 32, 256), 256>>>(bufP0, bufP1, rowP, srcP, dinvP, bp1, NP);
    k_gemm<<<cdiv(NP, TM), 256>>>(bufP1, Wp2, bufP0, NP, HF);
    k_aggregate<<<cdiv(NP * 32, 256), 256>>>(bufP0, bufP1, rowP, srcP, dinvP, bp2, NP);

    // ---- substrate GCN ----
    k_gemm<<<cdiv(NS, TM), 256>>>(x_s, Ws1, bufS0, NS, SD);
    k_aggregate<<<cdiv(NS * 32, 256), 256>>>(bufS0, bufS1, rowS, srcS, dinvS, bs1, NS);
    k_gemm<<<cdiv(NS, TM), 256>>>(bufS1, Ws2, bufS0, NS, HF);
    k_aggregate<<<cdiv(NS * 32, 256), 256>>>(bufS0, bufS1, rowS, srcS, dinvS, bs2, NS);

    // ---- per-node link features: Ap = z_p @ Wc_top, As = z_s @ Wc_bot ----
    k_gemm<<<cdiv(NP, TM), 256>>>(bufP1, Wc, bufP0, NP, HF);
    k_gemm<<<cdiv(NS, TM), 256>>>(bufS1, Wc + 64 * 64, bufS0, NS, HF);

    // ---- link prediction ----
    {
        long long threads = (long long)EL * 32;
        int blocks = (int)((threads + 255) / 256);
        k_link<<<blocks, 256>>>(bufP0, bufS0, ed_p, ed_s, Wc + 128 * 64, Wl2, bl2, out, EL);
    }
}